// round 10
// baseline (speedup 1.0000x reference)
#include <cuda_runtime.h>
#include <cuda_bf16.h>
#include <cuda_fp16.h>
#include <cstdint>

#define K_CODES 2048
#define DIM     256
#define NVEC    65536          // 64*32*32 vectors
#define QELEMS  16777216       // 64*256*1024 output elements
#define HW      1024           // 32*32
#define MARGIN  2e-3f

// ---------------- scratch (no allocations allowed) ----------------
__device__ int            g_idx[NVEC];
__device__ float          g_sx[NVEC];
__device__ float          g_sc[K_CODES];
__device__ __nv_bfloat16  g_cbh[K_CODES * DIM];        // codebook bf16 (hi only)
__device__ __half         g_dq[(size_t)NVEC * K_CODES];// approx scores (dist - sx), fp16
__device__ int            g_counts[K_CODES];
__device__ double         g_loss;

// ---------------- init ----------------
__global__ void k_init() {
    int t = blockIdx.x * blockDim.x + threadIdx.x;
    if (t < K_CODES) g_counts[t] = 0;
    if (t == 0) g_loss = 0.0;
}

// ---------------- codebook -> bf16 ----------------
__global__ void k_prep_cbh(const float* __restrict__ cb) {
    int e = blockIdx.x * blockDim.x + threadIdx.x;   // 0..524287
    g_cbh[e] = __float2bfloat16(cb[e]);
}

// ---------------- s_c[k] = sum_d c^2 (sequential, bit-stable) ----------------
__global__ void k_prep_sc(const float* __restrict__ cb) {
    int k = blockIdx.x * blockDim.x + threadIdx.x;
    const float* r = cb + k * DIM;
    float s = 0.f;
    for (int d = 0; d < DIM; d++) s = __fadd_rn(s, __fmul_rn(r[d], r[d]));
    g_sc[k] = s;
}

// ---------------- s_x[n] = sum_d x^2 (sequential ascending d) ----------------
__global__ void k_prep_sx(const float* __restrict__ x) {
    int bid = blockIdx.x;
    int b   = bid >> 2;
    int hw  = ((bid & 3) << 8) + threadIdx.x;
    const float* p = x + (size_t)b * DIM * HW + hw;
    float s = 0.f;
    for (int d = 0; d < DIM; d++) {
        float v = p[d * HW];
        s = __fadd_rn(s, __fmul_rn(v, v));
    }
    g_sx[(b << 10) + hw] = s;
}

// ================== sm_80-era PTX helpers (legal on compute_100) ==================
__device__ __forceinline__ uint32_t smem_u32(const void* p) {
    uint32_t a;
    asm("{ .reg .u64 t; cvta.to.shared.u64 t, %1; cvt.u32.u64 %0, t; }" : "=r"(a) : "l"(p));
    return a;
}
__device__ __forceinline__ void ldsm4(uint32_t& r0, uint32_t& r1, uint32_t& r2, uint32_t& r3,
                                      uint32_t addr) {
    asm volatile("ldmatrix.sync.aligned.m8n8.x4.shared.b16 {%0,%1,%2,%3}, [%4];"
                 : "=r"(r0), "=r"(r1), "=r"(r2), "=r"(r3) : "r"(addr));
}
__device__ __forceinline__ void mma16816(float* c,
                                         uint32_t a0, uint32_t a1, uint32_t a2, uint32_t a3,
                                         uint32_t b0, uint32_t b1) {
    asm volatile(
        "mma.sync.aligned.m16n8k16.row.col.f32.bf16.bf16.f32 "
        "{%0,%1,%2,%3}, {%4,%5,%6,%7}, {%8,%9}, {%0,%1,%2,%3};"
        : "+f"(c[0]), "+f"(c[1]), "+f"(c[2]), "+f"(c[3])
        : "r"(a0), "r"(a1), "r"(a2), "r"(a3), "r"(b0), "r"(b1));
}
__device__ __forceinline__ void cp16(uint32_t dst, const void* src) {
    asm volatile("cp.async.cg.shared.global [%0], [%1], 16;" :: "r"(dst), "l"(src));
}
#define CP_COMMIT() asm volatile("cp.async.commit_group;" ::: "memory")
#define CP_WAIT0()  asm volatile("cp.async.wait_group 0;"  ::: "memory")
#define CP_WAIT1()  asm volatile("cp.async.wait_group 1;"  ::: "memory")

// ---------------- SMEM layout (bytes) ----------------
#define OFF_AH   0          // 65536 : A hi, 128 rows x 512B (256 d bf16), swizzled
#define OFF_B    65536      // 2 bufs x 32768 : B hi, 64 codes x 512B each
#define OFF_SC   131072     // 4096  : sc[1024] f32 (this CTA's code half)
#define SMEM_TOTAL 135296

// swizzle: 16B-chunk c within 512B row r: phys chunk = c ^ (r&7)
__device__ __forceinline__ uint32_t swz(int r, int c) {
    return (uint32_t)r * 512u + (uint32_t)((c ^ (r & 7)) << 4);
}

// ---------------- phase 1: single-bf16 HMMA score GEMM ----------------
// Grid 1024: blockIdx = rb*2 + half. CTA: rows [rb*128,+128) x codes [half*1024,+1024).
// Stores a(k) = fl(sc_k - 2*dot_hi) as fp16 into g_dq[n][k]. No argmin here.
__launch_bounds__(256, 1)
__global__ void k_dist(const float* __restrict__ x) {
    extern __shared__ char smem[];
    const uint32_t sb = smem_u32(smem);
    const int tid  = threadIdx.x, lane = tid & 31, warp = tid >> 5;
    const int wm   = warp >> 1, wn = warp & 1;           // 4 warps in M, 2 in N

    const int rb   = blockIdx.x >> 1, half = blockIdx.x & 1;
    const int n0   = rb * 128;
    const int b    = n0 >> 10, hw0 = n0 & 1023;
    const int kofs = half << 10;

    float* sc_sm = (float*)(smem + OFF_SC);

    // ---- per-thread B-load addressing (8 x 16B chunks per 64-code tile) ----
    uint32_t bdst[8];
    const __nv_bfloat16* bsrc[8];
#pragma unroll
    for (int i = 0; i < 8; i++) {
        int c = tid + i * 256;                  // 0..2047
        int row = c >> 5, ch = c & 31;          // row<64
        bdst[i] = (uint32_t)OFF_B + swz(row, ch);
        bsrc[i] = g_cbh + ((kofs + row) << 8) + (ch << 3);
    }

    // ---- prefetch B tile 0 into buf 0 ----
#pragma unroll
    for (int i = 0; i < 8; i++) cp16(sb + bdst[i], bsrc[i]);
    CP_COMMIT();

    // ---- sc (this half) -> smem ----
#pragma unroll
    for (int c = tid; c < 1024; c += 256) sc_sm[c] = __ldg(&g_sc[kofs + c]);

    // ---- A load (hi only) -> smem (swizzled) ----
    {
        int r = tid & 127, hf = tid >> 7, r7 = r & 7;
        const float* px = x + (size_t)b * DIM * HW + hw0 + r;
        char* rowh = smem + OFF_AH + r * 512;
#pragma unroll 4
        for (int d = hf * 128; d < hf * 128 + 128; d += 2) {
            float v0 = __ldg(px + (size_t)d * HW);
            float v1 = __ldg(px + (size_t)(d + 1) * HW);
            __nv_bfloat162 hp = __halves2bfloat162(__float2bfloat16(v0), __float2bfloat16(v1));
            uint32_t off = (uint32_t)((((d >> 3) ^ r7) << 4) | ((d & 7) << 1));
            *(uint32_t*)(rowh + off) = *(uint32_t*)&hp;
        }
    }

    // ---- per-lane ldmatrix addressing ----
    const int aRow = wm * 32 + (lane & 15);
    const int a_r7 = aRow & 7, a_kl = lane >> 4;
    const uint32_t aH0 = sb + OFF_AH + aRow * 512;
    const uint32_t aH1 = aH0 + 16 * 512;
    const int bRow = wn * 32 + (lane & 7) + ((lane >> 4) << 3);
    const int b_r7 = bRow & 7, b_kl = (lane >> 3) & 1;
    const uint32_t bRowOff = (uint32_t)bRow * 512u;

    __syncthreads();    // A tile + sc visible

    uint32_t fah[2][8], fb[2][8];

#define LOAD_FRAGS(s, kc) do {                                                   \
        const uint32_t aoff_ = (uint32_t)(((2 * (kc) + a_kl) ^ a_r7) << 4);      \
        const uint32_t boff_ = (uint32_t)(((2 * (kc) + b_kl) ^ b_r7) << 4);      \
        ldsm4(fah[s][0], fah[s][1], fah[s][2], fah[s][3], aH0 + aoff_);          \
        ldsm4(fah[s][4], fah[s][5], fah[s][6], fah[s][7], aH1 + aoff_);          \
        ldsm4(fb[s][0], fb[s][1], fb[s][2], fb[s][3], bB1 + boff_);              \
        ldsm4(fb[s][4], fb[s][5], fb[s][6], fb[s][7], bB2 + boff_);              \
    } while (0)

#define DO_MMAS(s) do {                                                          \
        mma16816(acc[0][0], fah[s][0], fah[s][1], fah[s][2], fah[s][3], fb[s][0], fb[s][1]); \
        mma16816(acc[0][1], fah[s][0], fah[s][1], fah[s][2], fah[s][3], fb[s][2], fb[s][3]); \
        mma16816(acc[0][2], fah[s][0], fah[s][1], fah[s][2], fah[s][3], fb[s][4], fb[s][5]); \
        mma16816(acc[0][3], fah[s][0], fah[s][1], fah[s][2], fah[s][3], fb[s][6], fb[s][7]); \
        mma16816(acc[1][0], fah[s][4], fah[s][5], fah[s][6], fah[s][7], fb[s][0], fb[s][1]); \
        mma16816(acc[1][1], fah[s][4], fah[s][5], fah[s][6], fah[s][7], fb[s][2], fb[s][3]); \
        mma16816(acc[1][2], fah[s][4], fah[s][5], fah[s][6], fah[s][7], fb[s][4], fb[s][5]); \
        mma16816(acc[1][3], fah[s][4], fah[s][5], fah[s][6], fah[s][7], fb[s][6], fb[s][7]); \
    } while (0)

    for (int t = 0; t < 16; t++) {
        const int buf = t & 1;
        if (t < 15) {
            const uint32_t db = sb + (uint32_t)((buf ^ 1) * 32768);
            const int adv = (t + 1) * 16384;    // 64 codes * 256 d per tile
#pragma unroll
            for (int i = 0; i < 8; i++) cp16(db + bdst[i], bsrc[i] + adv);
            CP_COMMIT();
            CP_WAIT1();
        } else {
            CP_WAIT0();
        }
        __syncthreads();                        // tile t fully resident

        float acc[2][4][4];
#pragma unroll
        for (int mt = 0; mt < 2; mt++)
#pragma unroll
            for (int nt = 0; nt < 4; nt++)
#pragma unroll
                for (int j = 0; j < 4; j++) acc[mt][nt][j] = 0.f;

        const uint32_t bB1 = sb + (uint32_t)OFF_B + (uint32_t)(buf * 32768) + bRowOff;
        const uint32_t bB2 = bB1 + 16 * 512;

        LOAD_FRAGS(0, 0);
#pragma unroll
        for (int kc = 0; kc < 16; kc++) {
            const int cur = kc & 1;
            if (kc < 15) LOAD_FRAGS(cur ^ 1, kc + 1);
            DO_MMAS(cur);
        }

        // ---- epilogue: a(k) = fl(sc_k - 2*dot) -> fp16 store ----
        const int klb = t * 64 + wn * 32 + ((lane & 3) << 1);   // local code idx base
#pragma unroll
        for (int mt = 0; mt < 2; mt++)
#pragma unroll
            for (int hhalf = 0; hhalf < 2; hhalf++) {
                const int n_i = n0 + wm * 32 + mt * 16 + hhalf * 8 + (lane >> 2);
                __half2* drow = (__half2*)(g_dq + (size_t)n_i * K_CODES);
#pragma unroll
                for (int nt = 0; nt < 4; nt++) {
                    const int c0l = klb + nt * 8;
                    float v0 = __fadd_rn(sc_sm[c0l],
                                         -__fmul_rn(2.0f, acc[mt][nt][hhalf * 2 + 0]));
                    float v1 = __fadd_rn(sc_sm[c0l + 1],
                                         -__fmul_rn(2.0f, acc[mt][nt][hhalf * 2 + 1]));
                    drow[(kofs + c0l) >> 1] = __floats2half2_rn(v0, v1);
                }
            }
        __syncthreads();                        // compute(t) done before buf overwrite
    }
#undef LOAD_FRAGS
#undef DO_MMAS
}

// ---------------- phase 2: scan fp16 scores, rescore candidates exactly ----------------
// warp per vector; grid 8192 x 256 (8 warps/CTA, consecutive hw for L1 reuse on x).
__launch_bounds__(256, 8)
__global__ void k_pick(const float* __restrict__ x, const float* __restrict__ cb) {
    const int lane = threadIdx.x & 31, warp = threadIdx.x >> 5;
    const int n = blockIdx.x * 8 + warp;
    const int b = n >> 10, hw = n & 1023;

    // x row: lane holds d = lane + 32*m
    float xr[8];
    const float* px = x + (size_t)b * DIM * HW + hw;
#pragma unroll
    for (int m = 0; m < 8; m++) xr[m] = __ldg(px + (size_t)(lane + 32 * m) * HW);
    const float sx = __ldg(&g_sx[n]);

    const __half2* dn = (const __half2*)(g_dq + (size_t)n * K_CODES);

    // pass 1: min of approx scores
    float amin = 3.4e38f;
#pragma unroll 8
    for (int j = 0; j < 32; j++) {
        float2 f = __half22float2(dn[lane * 32 + j]);
        amin = fminf(amin, fminf(f.x, f.y));
    }
#pragma unroll
    for (int off = 16; off; off >>= 1)
        amin = fminf(amin, __shfl_xor_sync(0xffffffffu, amin, off));
    const float thr = amin + MARGIN;

    // pass 2: rescore candidates (warp-cooperative; ascending handled by tie-break)
    float best = 3.4e38f; int bi = 0x7fffffff;
    for (int j = 0; j < 32; j++) {
        float2 f = __half22float2(dn[lane * 32 + j]);
        unsigned bal = __ballot_sync(0xffffffffu, f.x <= thr || f.y <= thr);
        while (bal) {
            int src = __ffs(bal) - 1; bal &= bal - 1;
            float fx = __shfl_sync(0xffffffffu, f.x, src);
            float fy = __shfl_sync(0xffffffffu, f.y, src);
            int k0 = src * 64 + 2 * j;
#pragma unroll
            for (int pp = 0; pp < 2; pp++) {
                float fv = pp ? fy : fx;
                int   k  = k0 + pp;
                if (fv <= thr) {
                    const float* crow = cb + (size_t)k * DIM;
                    float p = 0.f;
#pragma unroll
                    for (int m = 0; m < 8; m++)
                        p = __fmaf_rn(xr[m], __ldg(crow + lane + 32 * m), p);
#pragma unroll
                    for (int off = 16; off; off >>= 1)
                        p += __shfl_xor_sync(0xffffffffu, p, off);
                    float u = __fadd_rn(sx, __ldg(&g_sc[k]));
                    float dist = __fadd_rn(u, -__fmul_rn(2.0f, p));
                    if (dist < best || (dist == best && k < bi)) { best = dist; bi = k; }
                }
            }
        }
    }
    if (lane == 0) g_idx[n] = bi;
}

// ---------------- idx output + counts ----------------
__global__ void k_idxcnt(float* __restrict__ oidx) {
    int t = blockIdx.x * blockDim.x + threadIdx.x;
    int k = g_idx[t];
    atomicAdd(&g_counts[k], 1);
    if (oidx) oidx[t] = (float)k;
}

// ---------------- quant gather + loss (smem-transposed, fully coalesced) ----------------
__global__ void k_out(const float* __restrict__ x, const float* __restrict__ cb,
                      float* __restrict__ outq) {
    __shared__ float q_sm[32][257];
    __shared__ int   kk[32];
    const int tid = threadIdx.x, lane = tid & 31, w = tid >> 5;
    const int b   = blockIdx.x >> 5;
    const int hw0 = (blockIdx.x & 31) << 5;

    if (tid < 32) kk[tid] = g_idx[(b << 10) + hw0 + tid];
    __syncthreads();

    {
        int r = tid >> 3, c4 = (tid & 7) << 2;
        const float4* src = (const float4*)(cb + kk[r] * DIM);
#pragma unroll
        for (int j = 0; j < 8; j++) {
            float4 v = __ldg(&src[(c4 >> 2) + j * 8]);
            int c = c4 + j * 32;
            q_sm[r][c + 0] = v.x; q_sm[r][c + 1] = v.y;
            q_sm[r][c + 2] = v.z; q_sm[r][c + 3] = v.w;
        }
    }
    __syncthreads();

    double ls = 0.0;
    const size_t base = (size_t)b * DIM * HW + hw0 + lane;
#pragma unroll 4
    for (int dd = 0; dd < 32; dd++) {
        int d = w * 32 + dd;
        float q  = q_sm[lane][d];
        size_t e = base + (size_t)d * HW;
        float xv = __ldg(&x[e]);
        outq[e] = q;
        float df = __fadd_rn(q, -xv);
        ls += (double)__fmul_rn(df, df);
    }
    for (int off = 16; off; off >>= 1) ls += __shfl_down_sync(0xffffffffu, ls, off);
    __shared__ double ws[8];
    if (lane == 0) ws[w] = ls;
    __syncthreads();
    if (tid == 0) {
        double s = 0.0;
        for (int i = 0; i < 8; i++) s += ws[i];
        atomicAdd(&g_loss, s);
    }
}

// ---------------- scalars: loss & perplexity ----------------
__global__ void k_fin(float* __restrict__ o_loss, float* __restrict__ o_perp) {
    __shared__ double ws[8];
    int tid = threadIdx.x;
    double s = 0.0;
    for (int k = tid; k < K_CODES; k += 256) {
        float p = (float)g_counts[k] / 65536.0f;
        float l = logf(__fadd_rn(p, 1e-10f));
        s += (double)__fmul_rn(p, l);
    }
    for (int off = 16; off; off >>= 1) s += __shfl_down_sync(0xffffffffu, s, off);
    if ((tid & 31) == 0) ws[tid >> 5] = s;
    __syncthreads();
    if (tid == 0) {
        double tot = 0.0;
        for (int i = 0; i < 8; i++) tot += ws[i];
        *o_perp = expf(-(float)tot);
        float m = (float)(g_loss / (double)QELEMS);
        *o_loss = __fadd_rn(m, __fmul_rn(0.25f, m));
    }
}

// ---------------- launch ----------------
extern "C" void kernel_launch(void* const* d_in, const int* in_sizes, int n_in,
                              void* d_out, int out_size) {
    const float* x  = (const float*)d_in[0];
    const float* cb = (const float*)d_in[1];
    if (n_in >= 2 && in_sizes[0] == K_CODES * DIM && in_sizes[1] == QELEMS) {
        x = (const float*)d_in[1]; cb = (const float*)d_in[0];
    }
    float* out = (float*)d_out;

    float* o_loss  = out;
    float* o_quant = out + 1;
    float* o_perp  = out + 1 + QELEMS;
    float* o_idx   = out + 2 + QELEMS;
    if (out_size == QELEMS) {
        o_quant = out; o_loss = nullptr; o_perp = nullptr; o_idx = nullptr;
    }

    cudaFuncSetAttribute(k_dist, cudaFuncAttributeMaxDynamicSharedMemorySize, SMEM_TOTAL);

    k_init    <<<8,    256>>>();
    k_prep_cbh<<<2048, 256>>>(cb);
    k_prep_sc <<<8,    256>>>(cb);
    k_prep_sx <<<256,  256>>>(x);
    k_dist    <<<1024, 256, SMEM_TOTAL>>>(x);
    k_pick    <<<8192, 256>>>(x, cb);
    k_idxcnt  <<<256,  256>>>(o_idx);
    k_out     <<<2048, 256>>>(x, cb, o_quant);
    if (o_loss) k_fin <<<1,   256>>>(o_loss, o_perp);
}

// round 12
// speedup vs baseline: 1.5874x; 1.5874x over previous
#include <cuda_runtime.h>
#include <cuda_bf16.h>
#include <cuda_fp16.h>
#include <cstdint>

#define K_CODES 2048
#define DIM     256
#define NVEC    65536          // 64*32*32 vectors
#define QELEMS  16777216       // 64*256*1024 output elements
#define HW      1024           // 32*32
#define MARGIN  2e-3f

// ---------------- scratch (no allocations allowed) ----------------
__device__ int            g_idx[NVEC];
__device__ float          g_sx[NVEC];
__device__ float          g_sc[K_CODES];
__device__ __nv_bfloat16  g_cbh[K_CODES * DIM];        // codebook bf16 (hi only)
__device__ __half         g_dq[(size_t)NVEC * K_CODES];// approx scores (dist - sx), fp16
__device__ int            g_counts[K_CODES];
__device__ double         g_loss;

// ---------------- init ----------------
__global__ void k_init() {
    int t = blockIdx.x * blockDim.x + threadIdx.x;
    if (t < K_CODES) g_counts[t] = 0;
    if (t == 0) g_loss = 0.0;
}

// ---------------- codebook -> bf16 ----------------
__global__ void k_prep_cbh(const float* __restrict__ cb) {
    int e = blockIdx.x * blockDim.x + threadIdx.x;   // 0..524287
    g_cbh[e] = __float2bfloat16(cb[e]);
}

// ---------------- s_c[k] = sum_d c^2 (sequential, bit-stable) ----------------
__global__ void k_prep_sc(const float* __restrict__ cb) {
    int k = blockIdx.x * blockDim.x + threadIdx.x;
    const float* r = cb + k * DIM;
    float s = 0.f;
    for (int d = 0; d < DIM; d++) s = __fadd_rn(s, __fmul_rn(r[d], r[d]));
    g_sc[k] = s;
}

// ---------------- s_x[n] = sum_d x^2 (sequential ascending d) ----------------
__global__ void k_prep_sx(const float* __restrict__ x) {
    int bid = blockIdx.x;
    int b   = bid >> 2;
    int hw  = ((bid & 3) << 8) + threadIdx.x;
    const float* p = x + (size_t)b * DIM * HW + hw;
    float s = 0.f;
    for (int d = 0; d < DIM; d++) {
        float v = p[d * HW];
        s = __fadd_rn(s, __fmul_rn(v, v));
    }
    g_sx[(b << 10) + hw] = s;
}

// ================== sm_80-era PTX helpers (legal on compute_100) ==================
__device__ __forceinline__ uint32_t smem_u32(const void* p) {
    uint32_t a;
    asm("{ .reg .u64 t; cvta.to.shared.u64 t, %1; cvt.u32.u64 %0, t; }" : "=r"(a) : "l"(p));
    return a;
}
__device__ __forceinline__ void ldsm4(uint32_t& r0, uint32_t& r1, uint32_t& r2, uint32_t& r3,
                                      uint32_t addr) {
    asm volatile("ldmatrix.sync.aligned.m8n8.x4.shared.b16 {%0,%1,%2,%3}, [%4];"
                 : "=r"(r0), "=r"(r1), "=r"(r2), "=r"(r3) : "r"(addr));
}
__device__ __forceinline__ void mma16816(float* c,
                                         uint32_t a0, uint32_t a1, uint32_t a2, uint32_t a3,
                                         uint32_t b0, uint32_t b1) {
    asm volatile(
        "mma.sync.aligned.m16n8k16.row.col.f32.bf16.bf16.f32 "
        "{%0,%1,%2,%3}, {%4,%5,%6,%7}, {%8,%9}, {%0,%1,%2,%3};"
        : "+f"(c[0]), "+f"(c[1]), "+f"(c[2]), "+f"(c[3])
        : "r"(a0), "r"(a1), "r"(a2), "r"(a3), "r"(b0), "r"(b1));
}
__device__ __forceinline__ void cp16(uint32_t dst, const void* src) {
    asm volatile("cp.async.cg.shared.global [%0], [%1], 16;" :: "r"(dst), "l"(src));
}
#define CP_COMMIT() asm volatile("cp.async.commit_group;" ::: "memory")
#define CP_WAIT0()  asm volatile("cp.async.wait_group 0;"  ::: "memory")
#define CP_WAIT1()  asm volatile("cp.async.wait_group 1;"  ::: "memory")

// ---------------- SMEM layout (bytes) ----------------
#define OFF_AH   0          // 65536 : A hi, 128 rows x 512B (256 d bf16), swizzled
#define OFF_B    65536      // 2 bufs x 32768 : B hi, 64 codes x 512B each
#define OFF_SC   131072     // 4096  : sc[1024] f32 (this CTA's code half)
#define OFF_STG  135168     // 18432 : score stage, 128 rows x 72 halves (144B, 16B-aligned)
#define SMEM_TOTAL 153600

// swizzle: 16B-chunk c within 512B row r: phys chunk = c ^ (r&7)
__device__ __forceinline__ uint32_t swz(int r, int c) {
    return (uint32_t)r * 512u + (uint32_t)((c ^ (r & 7)) << 4);
}

// ---------------- phase 1: single-bf16 HMMA score GEMM ----------------
// Grid 1024: blockIdx = rb*2 + half. CTA: rows [rb*128,+128) x codes [half*1024,+1024).
// Stores a(k) = fl(sc_k - 2*dot_hi) as fp16 into g_dq[n][k], coalesced via smem staging.
__launch_bounds__(256, 1)
__global__ void k_dist(const float* __restrict__ x) {
    extern __shared__ char smem[];
    const uint32_t sb = smem_u32(smem);
    const int tid  = threadIdx.x, lane = tid & 31, warp = tid >> 5;
    const int wm   = warp >> 1, wn = warp & 1;           // 4 warps in M, 2 in N

    const int rb   = blockIdx.x >> 1, half = blockIdx.x & 1;
    const int n0   = rb * 128;
    const int b    = n0 >> 10, hw0 = n0 & 1023;
    const int kofs = half << 10;

    float*  sc_sm = (float*)(smem + OFF_SC);
    __half* stage = (__half*)(smem + OFF_STG);

    // ---- per-thread B-load addressing (8 x 16B chunks per 64-code tile) ----
    uint32_t bdst[8];
    const __nv_bfloat16* bsrc[8];
#pragma unroll
    for (int i = 0; i < 8; i++) {
        int c = tid + i * 256;                  // 0..2047
        int row = c >> 5, ch = c & 31;          // row<64
        bdst[i] = (uint32_t)OFF_B + swz(row, ch);
        bsrc[i] = g_cbh + ((kofs + row) << 8) + (ch << 3);
    }

    // ---- prefetch B tile 0 into buf 0 ----
#pragma unroll
    for (int i = 0; i < 8; i++) cp16(sb + bdst[i], bsrc[i]);
    CP_COMMIT();

    // ---- sc (this half) -> smem ----
#pragma unroll
    for (int c = tid; c < 1024; c += 256) sc_sm[c] = __ldg(&g_sc[kofs + c]);

    // ---- A load (hi only) -> smem (swizzled) ----
    {
        int r = tid & 127, hf = tid >> 7, r7 = r & 7;
        const float* px = x + (size_t)b * DIM * HW + hw0 + r;
        char* rowh = smem + OFF_AH + r * 512;
#pragma unroll 4
        for (int d = hf * 128; d < hf * 128 + 128; d += 2) {
            float v0 = __ldg(px + (size_t)d * HW);
            float v1 = __ldg(px + (size_t)(d + 1) * HW);
            __nv_bfloat162 hp = __halves2bfloat162(__float2bfloat16(v0), __float2bfloat16(v1));
            uint32_t off = (uint32_t)((((d >> 3) ^ r7) << 4) | ((d & 7) << 1));
            *(uint32_t*)(rowh + off) = *(uint32_t*)&hp;
        }
    }

    // ---- per-lane ldmatrix addressing ----
    const int aRow = wm * 32 + (lane & 15);
    const int a_r7 = aRow & 7, a_kl = lane >> 4;
    const uint32_t aH0 = sb + OFF_AH + aRow * 512;
    const uint32_t aH1 = aH0 + 16 * 512;
    const int bRow = wn * 32 + (lane & 7) + ((lane >> 4) << 3);
    const int b_r7 = bRow & 7, b_kl = (lane >> 3) & 1;
    const uint32_t bRowOff = (uint32_t)bRow * 512u;

    __syncthreads();    // A tile + sc visible

    uint32_t fah[2][8], fb[2][8];

#define LOAD_FRAGS(s, kc) do {                                                   \
        const uint32_t aoff_ = (uint32_t)(((2 * (kc) + a_kl) ^ a_r7) << 4);      \
        const uint32_t boff_ = (uint32_t)(((2 * (kc) + b_kl) ^ b_r7) << 4);      \
        ldsm4(fah[s][0], fah[s][1], fah[s][2], fah[s][3], aH0 + aoff_);          \
        ldsm4(fah[s][4], fah[s][5], fah[s][6], fah[s][7], aH1 + aoff_);          \
        ldsm4(fb[s][0], fb[s][1], fb[s][2], fb[s][3], bB1 + boff_);              \
        ldsm4(fb[s][4], fb[s][5], fb[s][6], fb[s][7], bB2 + boff_);              \
    } while (0)

#define DO_MMAS(s) do {                                                          \
        mma16816(acc[0][0], fah[s][0], fah[s][1], fah[s][2], fah[s][3], fb[s][0], fb[s][1]); \
        mma16816(acc[0][1], fah[s][0], fah[s][1], fah[s][2], fah[s][3], fb[s][2], fb[s][3]); \
        mma16816(acc[0][2], fah[s][0], fah[s][1], fah[s][2], fah[s][3], fb[s][4], fb[s][5]); \
        mma16816(acc[0][3], fah[s][0], fah[s][1], fah[s][2], fah[s][3], fb[s][6], fb[s][7]); \
        mma16816(acc[1][0], fah[s][4], fah[s][5], fah[s][6], fah[s][7], fb[s][0], fb[s][1]); \
        mma16816(acc[1][1], fah[s][4], fah[s][5], fah[s][6], fah[s][7], fb[s][2], fb[s][3]); \
        mma16816(acc[1][2], fah[s][4], fah[s][5], fah[s][6], fah[s][7], fb[s][4], fb[s][5]); \
        mma16816(acc[1][3], fah[s][4], fah[s][5], fah[s][6], fah[s][7], fb[s][6], fb[s][7]); \
    } while (0)

    for (int t = 0; t < 16; t++) {
        const int buf = t & 1;
        if (t < 15) {
            const uint32_t db = sb + (uint32_t)((buf ^ 1) * 32768);
            const int adv = (t + 1) * 16384;    // 64 codes * 256 d per tile
#pragma unroll
            for (int i = 0; i < 8; i++) cp16(db + bdst[i], bsrc[i] + adv);
            CP_COMMIT();
            CP_WAIT1();
        } else {
            CP_WAIT0();
        }
        __syncthreads();                        // tile t resident; stage copy(t-1) done

        float acc[2][4][4];
#pragma unroll
        for (int mt = 0; mt < 2; mt++)
#pragma unroll
            for (int nt = 0; nt < 4; nt++)
#pragma unroll
                for (int j = 0; j < 4; j++) acc[mt][nt][j] = 0.f;

        const uint32_t bB1 = sb + (uint32_t)OFF_B + (uint32_t)(buf * 32768) + bRowOff;
        const uint32_t bB2 = bB1 + 16 * 512;

        LOAD_FRAGS(0, 0);
#pragma unroll
        for (int kc = 0; kc < 16; kc++) {
            const int cur = kc & 1;
            if (kc < 15) LOAD_FRAGS(cur ^ 1, kc + 1);
            DO_MMAS(cur);
        }

        // ---- epilogue: a(k) = fl(sc_k - 2*dot) -> staged fp16 ----
        const int klb  = t * 64 + wn * 32 + ((lane & 3) << 1);  // sc index base (local 1024)
        const int kloc = wn * 32 + ((lane & 3) << 1);           // stage col base (0..63)
#pragma unroll
        for (int mt = 0; mt < 2; mt++)
#pragma unroll
            for (int hhalf = 0; hhalf < 2; hhalf++) {
                const int n_local = wm * 32 + mt * 16 + hhalf * 8 + (lane >> 2);
                __half* srow = stage + n_local * 72;
#pragma unroll
                for (int nt = 0; nt < 4; nt++) {
                    const int c0l = klb + nt * 8;
                    float v0 = __fadd_rn(sc_sm[c0l],
                                         -__fmul_rn(2.0f, acc[mt][nt][hhalf * 2 + 0]));
                    float v1 = __fadd_rn(sc_sm[c0l + 1],
                                         -__fmul_rn(2.0f, acc[mt][nt][hhalf * 2 + 1]));
                    *(__half2*)(srow + kloc + nt * 8) = __floats2half2_rn(v0, v1);
                }
            }
        __syncthreads();                        // stage complete

        // ---- coalesced copy stage -> g_dq[n][kofs + t*64 .. +64] ----
        {
            const size_t kbase = (size_t)kofs + (size_t)t * 64;
#pragma unroll
            for (int i = 0; i < 4; i++) {
                int idx = tid + i * 256;        // 0..1023
                int row = idx >> 3, seg = idx & 7;
                uint4 v = *(uint4*)(stage + row * 72 + seg * 8);
                *(uint4*)(g_dq + (size_t)(n0 + row) * K_CODES + kbase + seg * 8) = v;
            }
        }
        __syncthreads();                        // copy done before B-buf/stage reuse
    }
#undef LOAD_FRAGS
#undef DO_MMAS
}

// ---------------- phase 2: scan fp16 scores (coalesced), rescore candidates ----------------
// warp per vector; grid 8192 x 256 (8 warps/CTA, consecutive hw -> shared x sectors).
__launch_bounds__(256, 8)
__global__ void k_pick(const float* __restrict__ x, const float* __restrict__ cb) {
    const int lane = threadIdx.x & 31, warp = threadIdx.x >> 5;
    const int n = blockIdx.x * 8 + warp;
    const int b = n >> 10, hw = n & 1023;

    // x row: lane holds d = lane + 32*m
    float xr[8];
    const float* px = x + (size_t)b * DIM * HW + hw;
#pragma unroll
    for (int m = 0; m < 8; m++) xr[m] = __ldg(px + (size_t)(lane + 32 * m) * HW);
    const float sx = __ldg(&g_sx[n]);

    const __half2* dn = (const __half2*)(g_dq + (size_t)n * K_CODES);

    // pass 1: min of approx scores (coalesced: lanes read consecutive half2)
    float amin = 3.4e38f;
#pragma unroll 8
    for (int j = 0; j < 32; j++) {
        float2 f = __half22float2(dn[j * 32 + lane]);
        amin = fminf(amin, fminf(f.x, f.y));
    }
#pragma unroll
    for (int off = 16; off; off >>= 1)
        amin = fminf(amin, __shfl_xor_sync(0xffffffffu, amin, off));
    const float thr = amin + MARGIN;

    // pass 2: rescore candidates exactly (warp-cooperative, ascending k via tie-break)
    float best = 3.4e38f; int bi = 0x7fffffff;
    for (int j = 0; j < 32; j++) {
        float2 f = __half22float2(dn[j * 32 + lane]);
        unsigned bal = __ballot_sync(0xffffffffu, f.x <= thr || f.y <= thr);
        while (bal) {
            int src = __ffs(bal) - 1; bal &= bal - 1;
            float fx = __shfl_sync(0xffffffffu, f.x, src);
            float fy = __shfl_sync(0xffffffffu, f.y, src);
            int k0 = j * 64 + src * 2;
#pragma unroll
            for (int pp = 0; pp < 2; pp++) {
                float fv = pp ? fy : fx;
                int   k  = k0 + pp;
                if (fv <= thr) {
                    const float* crow = cb + (size_t)k * DIM;
                    float p = 0.f;
#pragma unroll
                    for (int m = 0; m < 8; m++)
                        p = __fmaf_rn(xr[m], __ldg(crow + lane + 32 * m), p);
#pragma unroll
                    for (int off = 16; off; off >>= 1)
                        p += __shfl_xor_sync(0xffffffffu, p, off);
                    float u = __fadd_rn(sx, __ldg(&g_sc[k]));
                    float dist = __fadd_rn(u, -__fmul_rn(2.0f, p));
                    if (dist < best || (dist == best && k < bi)) { best = dist; bi = k; }
                }
            }
        }
    }
    if (lane == 0) g_idx[n] = bi;
}

// ---------------- idx output + counts ----------------
__global__ void k_idxcnt(float* __restrict__ oidx) {
    int t = blockIdx.x * blockDim.x + threadIdx.x;
    int k = g_idx[t];
    atomicAdd(&g_counts[k], 1);
    if (oidx) oidx[t] = (float)k;
}

// ---------------- quant gather + loss (smem-transposed, fully coalesced) ----------------
__global__ void k_out(const float* __restrict__ x, const float* __restrict__ cb,
                      float* __restrict__ outq) {
    __shared__ float q_sm[32][257];
    __shared__ int   kk[32];
    const int tid = threadIdx.x, lane = tid & 31, w = tid >> 5;
    const int b   = blockIdx.x >> 5;
    const int hw0 = (blockIdx.x & 31) << 5;

    if (tid < 32) kk[tid] = g_idx[(b << 10) + hw0 + tid];
    __syncthreads();

    {
        int r = tid >> 3, c4 = (tid & 7) << 2;
        const float4* src = (const float4*)(cb + kk[r] * DIM);
#pragma unroll
        for (int j = 0; j < 8; j++) {
            float4 v = __ldg(&src[(c4 >> 2) + j * 8]);
            int c = c4 + j * 32;
            q_sm[r][c + 0] = v.x; q_sm[r][c + 1] = v.y;
            q_sm[r][c + 2] = v.z; q_sm[r][c + 3] = v.w;
        }
    }
    __syncthreads();

    double ls = 0.0;
    const size_t base = (size_t)b * DIM * HW + hw0 + lane;
#pragma unroll 4
    for (int dd = 0; dd < 32; dd++) {
        int d = w * 32 + dd;
        float q  = q_sm[lane][d];
        size_t e = base + (size_t)d * HW;
        float xv = __ldg(&x[e]);
        outq[e] = q;
        float df = __fadd_rn(q, -xv);
        ls += (double)__fmul_rn(df, df);
    }
    for (int off = 16; off; off >>= 1) ls += __shfl_down_sync(0xffffffffu, ls, off);
    __shared__ double ws[8];
    if (lane == 0) ws[w] = ls;
    __syncthreads();
    if (tid == 0) {
        double s = 0.0;
        for (int i = 0; i < 8; i++) s += ws[i];
        atomicAdd(&g_loss, s);
    }
}

// ---------------- scalars: loss & perplexity ----------------
__global__ void k_fin(float* __restrict__ o_loss, float* __restrict__ o_perp) {
    __shared__ double ws[8];
    int tid = threadIdx.x;
    double s = 0.0;
    for (int k = tid; k < K_CODES; k += 256) {
        float p = (float)g_counts[k] / 65536.0f;
        float l = logf(__fadd_rn(p, 1e-10f));
        s += (double)__fmul_rn(p, l);
    }
    for (int off = 16; off; off >>= 1) s += __shfl_down_sync(0xffffffffu, s, off);
    if ((tid & 31) == 0) ws[tid >> 5] = s;
    __syncthreads();
    if (tid == 0) {
        double tot = 0.0;
        for (int i = 0; i < 8; i++) tot += ws[i];
        *o_perp = expf(-(float)tot);
        float m = (float)(g_loss / (double)QELEMS);
        *o_loss = __fadd_rn(m, __fmul_rn(0.25f, m));
    }
}

// ---------------- launch ----------------
extern "C" void kernel_launch(void* const* d_in, const int* in_sizes, int n_in,
                              void* d_out, int out_size) {
    const float* x  = (const float*)d_in[0];
    const float* cb = (const float*)d_in[1];
    if (n_in >= 2 && in_sizes[0] == K_CODES * DIM && in_sizes[1] == QELEMS) {
        x = (const float*)d_in[1]; cb = (const float*)d_in[0];
    }
    float* out = (float*)d_out;

    float* o_loss  = out;
    float* o_quant = out + 1;
    float* o_perp  = out + 1 + QELEMS;
    float* o_idx   = out + 2 + QELEMS;
    if (out_size == QELEMS) {
        o_quant = out; o_loss = nullptr; o_perp = nullptr; o_idx = nullptr;
    }

    cudaFuncSetAttribute(k_dist, cudaFuncAttributeMaxDynamicSharedMemorySize, SMEM_TOTAL);

    k_init    <<<8,    256>>>();
    k_prep_cbh<<<2048, 256>>>(cb);
    k_prep_sc <<<8,    256>>>(cb);
    k_prep_sx <<<256,  256>>>(x);
    k_dist    <<<1024, 256, SMEM_TOTAL>>>(x);
    k_pick    <<<8192, 256>>>(x, cb);
    k_idxcnt  <<<256,  256>>>(o_idx);
    k_out     <<<2048, 256>>>(x, cb, o_quant);
    if (o_loss) k_fin <<<1,   256>>>(o_loss, o_perp);
}